// round 13
// baseline (speedup 1.0000x reference)
#include <cuda_runtime.h>
#include <cuda_bf16.h>
#include <math.h>
#include <stdint.h>

#define BATCH 2048
#define NTOT  4096
#define LAT   2048
#define PROJ  256
#define KPG   2048          // K for gemm operands (bf16)
#define KPZ   256           // K for sim operand (bf16)
#define NCK1  32            // gemm1 chunks (2048/64)
#define NCKZ  4             // sim chunks (256/64)
#define SPLK2 4             // gemm2 split-K parts

// ---------------- device scratch (no runtime allocation allowed) -------------
__device__ __nv_bfloat16 g_A2[(size_t)NTOT * KPG];    // bf16(H)
__device__ __nv_bfloat16 g_B1s[(size_t)LAT * KPG];    // bf16(W1)
__device__ __nv_bfloat16 g_W2s[(size_t)PROJ * KPG];   // bf16(W2)
__device__ __nv_bfloat16 g_X2[(size_t)NTOT * KPG];    // bf16(relu(bn(X)))
__device__ __nv_bfloat16 g_Zs[(size_t)NTOT * KPZ];    // bf16(normalized Z)
__device__ __nv_bfloat16 g_Xb[(size_t)NTOT * LAT];    // bf16 X (pre-BN)
__device__ float g_Zp[(size_t)SPLK2 * NTOT * PROJ];   // split-K partials
__device__ float g_sum[2 * LAT];
__device__ float g_sumsq[2 * LAT];
__device__ float g_bna[2 * LAT];
__device__ float g_bnc[2 * LAT];
__device__ float g_S[NTOT];
__device__ float g_pos[NTOT];

// ---------------- PTX helpers (baseline ISA only) ----------------------------
__device__ __forceinline__ uint32_t smem_u32(const void* p) {
    return (uint32_t)__cvta_generic_to_shared(p);
}
__device__ __forceinline__ void cp16(uint32_t dst, const void* src) {
    asm volatile("cp.async.cg.shared.global [%0], [%1], 16;" :: "r"(dst), "l"(src));
}
__device__ __forceinline__ void cp_commit() { asm volatile("cp.async.commit_group;"); }
__device__ __forceinline__ void cp_wait1()  { asm volatile("cp.async.wait_group 1;"); }
__device__ __forceinline__ void cp_wait0()  { asm volatile("cp.async.wait_group 0;"); }
__device__ __forceinline__ void ldsm_x4(uint32_t a, uint32_t& r0, uint32_t& r1,
                                        uint32_t& r2, uint32_t& r3) {
    asm volatile("ldmatrix.sync.aligned.m8n8.x4.shared.b16 {%0,%1,%2,%3}, [%4];"
                 : "=r"(r0), "=r"(r1), "=r"(r2), "=r"(r3) : "r"(a));
}
__device__ __forceinline__ void mma16816(float* c, const uint32_t* a, const uint32_t* b) {
    asm volatile("mma.sync.aligned.m16n8k16.row.col.f32.bf16.bf16.f32 "
                 "{%0,%1,%2,%3}, {%4,%5,%6,%7}, {%8,%9}, {%0,%1,%2,%3};"
                 : "+f"(c[0]), "+f"(c[1]), "+f"(c[2]), "+f"(c[3])
                 : "r"(a[0]), "r"(a[1]), "r"(a[2]), "r"(a[3]), "r"(b[0]), "r"(b[1]));
}

// FMA-only exp for y in ~[-4.1, 0.1]
__device__ __forceinline__ float fexp(float y) {
    float t = y * 1.4426950408889634f;
    float n = rintf(t);
    float f = t - n;
    float p =              1.5403530e-4f;
    p = fmaf(p, f, 1.3333558e-3f);
    p = fmaf(p, f, 9.6181291e-3f);
    p = fmaf(p, f, 5.5504109e-2f);
    p = fmaf(p, f, 2.4022651e-1f);
    p = fmaf(p, f, 6.9314718e-1f);
    p = fmaf(p, f, 1.0f);
    int e = ((int)n + 127) << 23;
    return p * __int_as_float(e);
}

__device__ __forceinline__ __nv_bfloat162 cvt2(const float2 v) {
    __nv_bfloat162 r; r.x = __float2bfloat16(v.x); r.y = __float2bfloat16(v.y);
    return r;
}
__device__ __forceinline__ uint2 cvt4(const float4 v) {
    __nv_bfloat162 lo = cvt2(make_float2(v.x, v.y));
    __nv_bfloat162 hi = cvt2(make_float2(v.z, v.w));
    uint2 r;
    r.x = *(const uint32_t*)&lo;
    r.y = *(const uint32_t*)&hi;
    return r;
}
__device__ __forceinline__ uint4 cvt8(const float4 v0, const float4 v1) {
    uint2 a = cvt4(v0), b = cvt4(v1);
    uint4 r; r.x = a.x; r.y = a.y; r.z = b.x; r.w = b.y;
    return r;
}

// ---------------- conversion: H, W1, W2 -> bf16, 8 elems/thread; init folded --
__global__ void cvt_all_kernel(const float* __restrict__ hi_,
                               const float* __restrict__ hj_,
                               const float* __restrict__ W1,
                               const float* __restrict__ W2) {
    size_t i = (size_t)blockIdx.x * 256 + threadIdx.x;   // 8-elem group index
    if (i < NTOT) g_S[i] = 0.f;
    if (i < 2 * LAT) { g_sum[i] = 0.f; g_sumsq[i] = 0.f; }
    const size_t nH  = (size_t)NTOT * 256;               // H groups
    const size_t nW1 = (size_t)LAT * 256;                // W1 groups
    if (i < nH) {
        const size_t half = (size_t)BATCH * 256;
        const float4* src = (i < half) ? (const float4*)hi_ + 2 * i
                                       : (const float4*)hj_ + 2 * (i - half);
        ((uint4*)g_A2)[i] = cvt8(src[0], src[1]);
    } else if (i < nH + nW1) {
        size_t j = i - nH;
        const float4* src = (const float4*)W1 + 2 * j;
        ((uint4*)g_B1s)[j] = cvt8(src[0], src[1]);
    } else {
        size_t j = i - nH - nW1;                         // W2: PROJ*256 groups
        const float4* src = (const float4*)W2 + 2 * j;
        ((uint4*)g_W2s)[j] = cvt8(src[0], src[1]);
    }
}

// ---------------- 8-warp bf16 MMA mainloop (gemm2 + sim) ----------------------
template <int KPHYS, int KH>
__device__ __forceinline__ void mma_mainloop(const __nv_bfloat16* __restrict__ A,
                                             const __nv_bfloat16* __restrict__ B,
                                             int m0, int n0, int c0, int nck,
                                             float acc[4][4][4]) {
    extern __shared__ char smem[];
    const uint32_t sb = smem_u32(smem);
    const int tid  = threadIdx.x;
    const int lane = tid & 31;
    const int w    = tid >> 5;
    const int wm   = w & 1;
    const int wn   = w >> 1;

    auto load_tile = [&](int c) {
        const int cl = c0 + c;
        const int kA = ((cl < 2 * KH) ? cl : cl - 2 * KH) * 64;
        const int kB = ((cl < KH) ? cl : cl - KH) * 64;
        const uint32_t sA = sb + (uint32_t)(c % 3) * 32768u;
        const uint32_t sB = sA + 16384u;
#pragma unroll
        for (int i = 0; i < 4; i++) {
            int idx = i * 256 + tid;
            int row = idx >> 3, ch = idx & 7;
            uint32_t dst = (uint32_t)row * 128 + (uint32_t)((ch ^ (row & 7)) * 16);
            cp16(sA + dst, A + (size_t)(m0 + row) * KPHYS + kA + ch * 8);
            cp16(sB + dst, B + (size_t)(n0 + row) * KPHYS + kB + ch * 8);
        }
        cp_commit();
    };

#pragma unroll
    for (int i = 0; i < 4; i++)
#pragma unroll
        for (int j = 0; j < 4; j++)
#pragma unroll
            for (int q = 0; q < 4; q++) acc[i][j][q] = 0.f;

    const int rA   = wm * 64 + (lane & 15);
    const int khA  = lane >> 4;
    const int rB   = wn * 32 + ((lane >> 4) << 3) + (lane & 7);
    const int khB  = (lane >> 3) & 1;
    const int rlow = lane & 7;

    load_tile(0);
    load_tile(1);

    for (int c = 0; c < nck; c++) {
        if (c < nck - 1) cp_wait1(); else cp_wait0();
        __syncthreads();
        if (c + 2 < nck) load_tile(c + 2);
        const uint32_t sA = sb + (uint32_t)(c % 3) * 32768u;
        const uint32_t sB = sA + 16384u;
#pragma unroll
        for (int ks = 0; ks < 4; ks++) {
            uint32_t af[4][4], bf[4][2];
#pragma unroll
            for (int mi = 0; mi < 4; mi++) {
                uint32_t a = sA + (uint32_t)(rA + mi * 16) * 128
                           + (uint32_t)((((ks * 2) + khA) ^ rlow) * 16);
                ldsm_x4(a, af[mi][0], af[mi][1], af[mi][2], af[mi][3]);
            }
#pragma unroll
            for (int np = 0; np < 2; np++) {
                uint32_t r0, r1, r2, r3;
                uint32_t a = sB + (uint32_t)(rB + np * 16) * 128
                           + (uint32_t)((((ks * 2) + khB) ^ rlow) * 16);
                ldsm_x4(a, r0, r1, r2, r3);
                bf[np * 2 + 0][0] = r0; bf[np * 2 + 0][1] = r1;
                bf[np * 2 + 1][0] = r2; bf[np * 2 + 1][1] = r3;
            }
#pragma unroll
            for (int mi = 0; mi < 4; mi++)
#pragma unroll
                for (int nf = 0; nf < 4; nf++)
                    mma16816(acc[mi][nf], af[mi], bf[nf]);
        }
    }
}

// ---------------- GEMM1: bf16, 4-warp, ks-pipelined fragments (+BN stats) ----
__global__ __launch_bounds__(128, 2) void gemm1_mma_kernel() {
    extern __shared__ char smem[];
    const uint32_t sb = smem_u32(smem);
    const int tid  = threadIdx.x;
    const int lane = tid & 31;
    const int w    = tid >> 5;
    const int wm   = w & 1;
    const int wn   = w >> 1;
    const int m0 = blockIdx.y * 128, n0 = blockIdx.x * 128;

    auto load_tile = [&](int c) {
        const int k0 = c * 64;
        const uint32_t sA = sb + (uint32_t)(c % 3) * 32768u;
        const uint32_t sB = sA + 16384u;
#pragma unroll
        for (int i = 0; i < 8; i++) {
            int idx = i * 128 + tid;
            int row = idx >> 3, ch = idx & 7;
            uint32_t dst = (uint32_t)row * 128 + (uint32_t)((ch ^ (row & 7)) * 16);
            cp16(sA + dst, g_A2 + (size_t)(m0 + row) * KPG + k0 + ch * 8);
            cp16(sB + dst, g_B1s + (size_t)(n0 + row) * KPG + k0 + ch * 8);
        }
        cp_commit();
    };

    float acc[4][8][4];
#pragma unroll
    for (int i = 0; i < 4; i++)
#pragma unroll
        for (int j = 0; j < 8; j++)
#pragma unroll
            for (int q = 0; q < 4; q++) acc[i][j][q] = 0.f;

    const int rA   = wm * 64 + (lane & 15);
    const int khA  = lane >> 4;
    const int rB   = wn * 64 + ((lane >> 4) << 3) + (lane & 7);
    const int khB  = (lane >> 3) & 1;
    const int rlow = lane & 7;

    auto ldfrags = [&](uint32_t sA, uint32_t sB, int ks,
                       uint32_t af[4][4], uint32_t bf[8][2]) {
#pragma unroll
        for (int mi = 0; mi < 4; mi++) {
            uint32_t a = sA + (uint32_t)(rA + mi * 16) * 128
                       + (uint32_t)((((ks * 2) + khA) ^ rlow) * 16);
            ldsm_x4(a, af[mi][0], af[mi][1], af[mi][2], af[mi][3]);
        }
#pragma unroll
        for (int np = 0; np < 4; np++) {
            uint32_t r0, r1, r2, r3;
            uint32_t a = sB + (uint32_t)(rB + np * 16) * 128
                       + (uint32_t)((((ks * 2) + khB) ^ rlow) * 16);
            ldsm_x4(a, r0, r1, r2, r3);
            bf[np * 2 + 0][0] = r0; bf[np * 2 + 0][1] = r1;
            bf[np * 2 + 1][0] = r2; bf[np * 2 + 1][1] = r3;
        }
    };

    load_tile(0);
    load_tile(1);

    for (int c = 0; c < NCK1; c++) {
        if (c < NCK1 - 1) cp_wait1(); else cp_wait0();
        __syncthreads();
        if (c + 2 < NCK1) load_tile(c + 2);
        const uint32_t sA = sb + (uint32_t)(c % 3) * 32768u;
        const uint32_t sB = sA + 16384u;

        uint32_t af[2][4][4], bf[2][8][2];
        ldfrags(sA, sB, 0, af[0], bf[0]);
#pragma unroll
        for (int ks = 0; ks < 4; ks++) {
            const int cur = ks & 1, nxt = cur ^ 1;
            if (ks < 3) ldfrags(sA, sB, ks + 1, af[nxt], bf[nxt]);
#pragma unroll
            for (int mi = 0; mi < 4; mi++)
#pragma unroll
                for (int nf = 0; nf < 8; nf++)
                    mma16816(acc[mi][nf], af[cur][mi], bf[cur][nf]);
        }
    }

#pragma unroll
    for (int mi = 0; mi < 4; mi++) {
        int row = m0 + wm * 64 + mi * 16 + (lane >> 2);
#pragma unroll
        for (int nf = 0; nf < 8; nf++) {
            int col = n0 + wn * 64 + nf * 8 + (lane & 3) * 2;
            *(__nv_bfloat162*)(g_Xb + (size_t)row * LAT + col) =
                cvt2(make_float2(acc[mi][nf][0], acc[mi][nf][1]));
            *(__nv_bfloat162*)(g_Xb + (size_t)(row + 8) * LAT + col) =
                cvt2(make_float2(acc[mi][nf][2], acc[mi][nf][3]));
        }
    }
    const int g = m0 >> 11;
#pragma unroll
    for (int nf = 0; nf < 8; nf++) {
#pragma unroll
        for (int q = 0; q < 2; q++) {
            float s = 0.f, sq = 0.f;
#pragma unroll
            for (int mi = 0; mi < 4; mi++) {
                float v0 = acc[mi][nf][q];
                float v1 = acc[mi][nf][q + 2];
                s += v0 + v1;
                sq = fmaf(v0, v0, sq);
                sq = fmaf(v1, v1, sq);
            }
#pragma unroll
            for (int off = 4; off <= 16; off <<= 1) {
                s  += __shfl_xor_sync(0xffffffffu, s, off);
                sq += __shfl_xor_sync(0xffffffffu, sq, off);
            }
            if ((lane >> 2) == 0) {
                int col = n0 + wn * 64 + nf * 8 + (lane & 3) * 2 + q;
                atomicAdd(&g_sum[g * LAT + col], s);
                atomicAdd(&g_sumsq[g * LAT + col], sq);
            }
        }
    }
}

// ---------------- GEMM2 (8-warp bf16 core, split-K=4) -------------------------
__global__ __launch_bounds__(256, 2) void gemm2_mma_kernel() {
    float acc[4][4][4];
    const int z  = blockIdx.z;
    const int m0 = blockIdx.y * 128, n0 = blockIdx.x * 128;
    mma_mainloop<KPG, 32>(g_X2, g_W2s, m0, n0, z * 8, 8, acc);
    float* out = g_Zp + (size_t)z * NTOT * PROJ;
    const int lane = threadIdx.x & 31, w = threadIdx.x >> 5;
    const int wm = w & 1, wn = w >> 1;
#pragma unroll
    for (int mi = 0; mi < 4; mi++) {
        int row = m0 + wm * 64 + mi * 16 + (lane >> 2);
#pragma unroll
        for (int nf = 0; nf < 4; nf++) {
            int col = n0 + wn * 32 + nf * 8 + (lane & 3) * 2;
            *(float2*)(out + (size_t)row * PROJ + col) =
                make_float2(acc[mi][nf][0], acc[mi][nf][1]);
            *(float2*)(out + (size_t)(row + 8) * PROJ + col) =
                make_float2(acc[mi][nf][2], acc[mi][nf][3]);
        }
    }
}

// ---------------- BN finalize ---------------------------------------------------
__global__ void bnfinal_kernel(const float* __restrict__ gamma,
                               const float* __restrict__ beta) {
    int idx = blockIdx.x * 256 + threadIdx.x;
    int c = idx & (LAT - 1);
    const float inv = 1.0f / (float)BATCH;
    float mu  = g_sum[idx] * inv;
    float var = g_sumsq[idx] * inv - mu * mu;
    float a = gamma[c] * rsqrtf(var + 1e-5f);
    g_bna[idx] = a;
    g_bnc[idx] = beta[c] - mu * a;
}

// ---------------- fused BN + ReLU, 16 elems/thread (2 rows x 8 cols) ----------
__global__ void bnrelu_kernel() {
    size_t i = (size_t)blockIdx.x * 256 + threadIdx.x;   // 2-row x 8-col group
    int pr = (int)(i >> 8);                              // pair-row 0..2047
    int g  = pr >> 10;                                   // group of row 2*pr
    int c0 = ((int)i & 255) * 8;
    const float4* A4 = (const float4*)(g_bna + g * LAT + c0);
    const float4* C4 = (const float4*)(g_bnc + g * LAT + c0);
    float4 a0 = A4[0], a1 = A4[1];
    float4 k0 = C4[0], k1 = C4[1];
    const size_t base = ((size_t)(2 * pr) * LAT + c0) >> 3;   // uint4 index
    const uint4* X4 = (const uint4*)g_Xb;
    uint4* O4 = (uint4*)g_X2;

    auto proc = [&](uint4 xb) {
        uint4 out;
        {
            __nv_bfloat162 x = *(const __nv_bfloat162*)&xb.x;
            __nv_bfloat162 r = cvt2(make_float2(
                fmaxf(fmaf(__bfloat162float(x.x), a0.x, k0.x), 0.f),
                fmaxf(fmaf(__bfloat162float(x.y), a0.y, k0.y), 0.f)));
            out.x = *(const uint32_t*)&r;
        }
        {
            __nv_bfloat162 x = *(const __nv_bfloat162*)&xb.y;
            __nv_bfloat162 r = cvt2(make_float2(
                fmaxf(fmaf(__bfloat162float(x.x), a0.z, k0.z), 0.f),
                fmaxf(fmaf(__bfloat162float(x.y), a0.w, k0.w), 0.f)));
            out.y = *(const uint32_t*)&r;
        }
        {
            __nv_bfloat162 x = *(const __nv_bfloat162*)&xb.z;
            __nv_bfloat162 r = cvt2(make_float2(
                fmaxf(fmaf(__bfloat162float(x.x), a1.x, k1.x), 0.f),
                fmaxf(fmaf(__bfloat162float(x.y), a1.y, k1.y), 0.f)));
            out.z = *(const uint32_t*)&r;
        }
        {
            __nv_bfloat162 x = *(const __nv_bfloat162*)&xb.w;
            __nv_bfloat162 r = cvt2(make_float2(
                fmaxf(fmaf(__bfloat162float(x.x), a1.z, k1.z), 0.f),
                fmaxf(fmaf(__bfloat162float(x.y), a1.w, k1.w), 0.f)));
            out.w = *(const uint32_t*)&r;
        }
        return out;
    };
    O4[base]       = proc(X4[base]);
    O4[base + 256] = proc(X4[base + 256]);   // next row: 256 uint4 per row
}

// ---------------- rownorm: sum 4 split-K parts + bias, normalize, emit bf16 ---
__global__ void rownorm_kernel(const float* __restrict__ b2) {
    int row  = blockIdx.x * 8 + (threadIdx.x >> 5);
    int lane = threadIdx.x & 31;
    const float4* bb = (const float4*)b2;
    float4 v0, v1;
    {
        float4 c = bb[lane], f = bb[lane + 32];
        v0 = c; v1 = f;
#pragma unroll
        for (int z = 0; z < SPLK2; z++) {
            const float4* p = (const float4*)(g_Zp + ((size_t)z * NTOT + row) * PROJ);
            float4 a = p[lane], d = p[lane + 32];
            v0.x += a.x; v0.y += a.y; v0.z += a.z; v0.w += a.w;
            v1.x += d.x; v1.y += d.y; v1.z += d.z; v1.w += d.w;
        }
    }
    float ss = v0.x * v0.x + v0.y * v0.y + v0.z * v0.z + v0.w * v0.w
             + v1.x * v1.x + v1.y * v1.y + v1.z * v1.z + v1.w * v1.w;
#pragma unroll
    for (int off = 16; off; off >>= 1) ss += __shfl_xor_sync(0xffffffffu, ss, off);
    float s = 1.41421356237f / fmaxf(sqrtf(ss), 1e-8f);   // sqrt(1/TEMP)/||z||
    v0.x *= s; v0.y *= s; v0.z *= s; v0.w *= s;
    v1.x *= s; v1.y *= s; v1.z *= s; v1.w *= s;

    __nv_bfloat162* Z = (__nv_bfloat162*)(g_Zs + (size_t)row * KPZ);
    Z[lane * 2 + 0]        = cvt2(make_float2(v0.x, v0.y));
    Z[lane * 2 + 1]        = cvt2(make_float2(v0.z, v0.w));
    Z[(lane + 32) * 2 + 0] = cvt2(make_float2(v1.x, v1.y));
    Z[(lane + 32) * 2 + 1] = cvt2(make_float2(v1.z, v1.w));
}

// ---------------- symmetric tensorized sim + online exp-sum ------------------
// 528 linear blocks -> upper-triangle (a, b) decode.
__global__ __launch_bounds__(256, 2) void sim_mma_kernel() {
    int rem = blockIdx.x, a = 0;
    while (rem >= 32 - a) { rem -= 32 - a; a++; }
    const int b = a + rem;
    float acc[4][4][4];
    const int i0 = a * 128, j0 = b * 128;
    mma_mainloop<KPZ, 4>(g_Zs, g_Zs, i0, j0, 0, NCKZ, acc);

    const int lane = threadIdx.x & 31, w = threadIdx.x >> 5;
    const int wm = w & 1, wn = w >> 1;
    const int lr = lane >> 2;
    const int lc = (lane & 3) * 2;
    const bool offd = (a != b);

    float cs[4][2];
#pragma unroll
    for (int nf = 0; nf < 4; nf++) { cs[nf][0] = 0.f; cs[nf][1] = 0.f; }

#pragma unroll
    for (int mi = 0; mi < 4; mi++) {
        int row0 = i0 + wm * 64 + mi * 16 + lr;
        int row1 = row0 + 8;
        int p0 = (row0 < BATCH) ? row0 + BATCH : row0 - BATCH;
        int p1 = (row1 < BATCH) ? row1 + BATCH : row1 - BATCH;
        float rs0 = 0.f, rs1 = 0.f;
#pragma unroll
        for (int nf = 0; nf < 4; nf++) {
            int col = j0 + wn * 32 + nf * 8 + lc;
            float d00 = acc[mi][nf][0], d01 = acc[mi][nf][1];
            float d10 = acc[mi][nf][2], d11 = acc[mi][nf][3];
            if (col == p0)     { g_pos[row0] = d00; g_pos[col]     = d00; }
            if (col + 1 == p0) { g_pos[row0] = d01; g_pos[col + 1] = d01; }
            if (col == p1)     { g_pos[row1] = d10; g_pos[col]     = d10; }
            if (col + 1 == p1) { g_pos[row1] = d11; g_pos[col + 1] = d11; }
            float e00 = (col     != row0) ? fexp(d00 - 2.f) : 0.f;
            float e01 = (col + 1 != row0) ? fexp(d01 - 2.f) : 0.f;
            float e10 = (col     != row1) ? fexp(d10 - 2.f) : 0.f;
            float e11 = (col + 1 != row1) ? fexp(d11 - 2.f) : 0.f;
            rs0 += e00 + e01;
            rs1 += e10 + e11;
            if (offd) { cs[nf][0] += e00 + e10; cs[nf][1] += e01 + e11; }
        }
        rs0 += __shfl_xor_sync(0xffffffffu, rs0, 1);
        rs0 += __shfl_xor_sync(0xffffffffu, rs0, 2);
        rs1 += __shfl_xor_sync(0xffffffffu, rs1, 1);
        rs1 += __shfl_xor_sync(0xffffffffu, rs1, 2);
        if ((lane & 3) == 0) {
            atomicAdd(&g_S[row0], rs0);
            atomicAdd(&g_S[row1], rs1);
        }
    }
    if (offd) {
#pragma unroll
        for (int nf = 0; nf < 4; nf++) {
#pragma unroll
            for (int q = 0; q < 2; q++) {
                float v = cs[nf][q];
                v += __shfl_xor_sync(0xffffffffu, v, 4);
                v += __shfl_xor_sync(0xffffffffu, v, 8);
                v += __shfl_xor_sync(0xffffffffu, v, 16);
                if (lr == 0)
                    atomicAdd(&g_S[j0 + wn * 32 + nf * 8 + lc + q], v);
            }
        }
    }
}

// ---------------- final reduction --------------------------------------------
__global__ void loss_kernel(float* __restrict__ out) {
    __shared__ float red[256];
    int t = threadIdx.x;
    float s = 0.f;
    for (int i = t; i < NTOT; i += 256)
        s += 2.0f + logf(g_S[i]) - g_pos[i];
    red[t] = s;
    __syncthreads();
    for (int off = 128; off; off >>= 1) {
        if (t < off) red[t] += red[t + off];
        __syncthreads();
    }
    if (t == 0) out[0] = red[0] / (float)NTOT;
}

// ---------------- launch ------------------------------------------------------
extern "C" void kernel_launch(void* const* d_in, const int* in_sizes, int n_in,
                              void* d_out, int out_size) {
    const float* h_i   = (const float*)d_in[0];
    const float* h_j   = (const float*)d_in[1];
    const float* W1    = (const float*)d_in[2];
    const float* gamma = (const float*)d_in[3];
    const float* beta  = (const float*)d_in[4];
    const float* W2    = (const float*)d_in[5];
    const float* b2    = (const float*)d_in[6];
    float* out = (float*)d_out;

    const int GEMM_SMEM = 3 * 32768;   // 98304
    cudaFuncSetAttribute(gemm1_mma_kernel, cudaFuncAttributeMaxDynamicSharedMemorySize, GEMM_SMEM);
    cudaFuncSetAttribute(gemm2_mma_kernel, cudaFuncAttributeMaxDynamicSharedMemorySize, GEMM_SMEM);
    cudaFuncSetAttribute(sim_mma_kernel,   cudaFuncAttributeMaxDynamicSharedMemorySize, GEMM_SMEM);

    const int CVT_GROUPS = (NTOT + LAT + PROJ) * 256;    // 8-elem groups
    cvt_all_kernel<<<CVT_GROUPS / 256, 256>>>(h_i, h_j, W1, W2);
    gemm1_mma_kernel<<<dim3(16, 32), 128, GEMM_SMEM>>>();
    bnfinal_kernel<<<16, 256>>>(gamma, beta);
    bnrelu_kernel<<<NTOT * 128 / 256, 256>>>();
    gemm2_mma_kernel<<<dim3(2, 32, SPLK2), 256, GEMM_SMEM>>>();
    rownorm_kernel<<<512, 256>>>(b2);
    sim_mma_kernel<<<528, 256, GEMM_SMEM>>>();
    loss_kernel<<<1, 256>>>(out);
}

// round 14
// speedup vs baseline: 1.4554x; 1.4554x over previous
#include <cuda_runtime.h>
#include <cuda_bf16.h>
#include <math.h>
#include <stdint.h>

#define BATCH 2048
#define NTOT  4096
#define LAT   2048
#define PROJ  256
#define KPG   2048          // K for gemm operands (bf16)
#define KPZ   256           // K for sim operand (bf16)
#define NCK1  32            // gemm1 chunks (2048/64)
#define NCKZ  4             // sim chunks (256/64)
#define SPLK2 4             // gemm2 split-K parts

// ---------------- device scratch (no runtime allocation allowed) -------------
__device__ __nv_bfloat16 g_A2[(size_t)NTOT * KPG];    // bf16(H)
__device__ __nv_bfloat16 g_B1s[(size_t)LAT * KPG];    // bf16(W1)
__device__ __nv_bfloat16 g_W2s[(size_t)PROJ * KPG];   // bf16(W2)
__device__ __nv_bfloat16 g_X2[(size_t)NTOT * KPG];    // bf16(relu(bn(X)))
__device__ __nv_bfloat16 g_Zs[(size_t)NTOT * KPZ];    // bf16(normalized Z)
__device__ __nv_bfloat16 g_Xb[(size_t)NTOT * LAT];    // bf16 X (pre-BN)
__device__ float g_Zp[(size_t)SPLK2 * NTOT * PROJ];   // split-K partials
__device__ float g_sum[2 * LAT];
__device__ float g_sumsq[2 * LAT];
__device__ float g_bna[2 * LAT];
__device__ float g_bnc[2 * LAT];
__device__ float g_S[NTOT];
__device__ float g_pos[NTOT];

// ---------------- PTX helpers (baseline ISA only) ----------------------------
__device__ __forceinline__ uint32_t smem_u32(const void* p) {
    return (uint32_t)__cvta_generic_to_shared(p);
}
__device__ __forceinline__ void cp16(uint32_t dst, const void* src) {
    asm volatile("cp.async.cg.shared.global [%0], [%1], 16;" :: "r"(dst), "l"(src));
}
__device__ __forceinline__ void cp_commit() { asm volatile("cp.async.commit_group;"); }
__device__ __forceinline__ void cp_wait1()  { asm volatile("cp.async.wait_group 1;"); }
__device__ __forceinline__ void cp_wait0()  { asm volatile("cp.async.wait_group 0;"); }
__device__ __forceinline__ void ldsm_x4(uint32_t a, uint32_t& r0, uint32_t& r1,
                                        uint32_t& r2, uint32_t& r3) {
    asm volatile("ldmatrix.sync.aligned.m8n8.x4.shared.b16 {%0,%1,%2,%3}, [%4];"
                 : "=r"(r0), "=r"(r1), "=r"(r2), "=r"(r3) : "r"(a));
}
__device__ __forceinline__ void mma16816(float* c, const uint32_t* a, const uint32_t* b) {
    asm volatile("mma.sync.aligned.m16n8k16.row.col.f32.bf16.bf16.f32 "
                 "{%0,%1,%2,%3}, {%4,%5,%6,%7}, {%8,%9}, {%0,%1,%2,%3};"
                 : "+f"(c[0]), "+f"(c[1]), "+f"(c[2]), "+f"(c[3])
                 : "r"(a[0]), "r"(a[1]), "r"(a[2]), "r"(a[3]), "r"(b[0]), "r"(b[1]));
}

// FMA-only exp for y in ~[-4.1, 0.1]
__device__ __forceinline__ float fexp(float y) {
    float t = y * 1.4426950408889634f;
    float n = rintf(t);
    float f = t - n;
    float p =              1.5403530e-4f;
    p = fmaf(p, f, 1.3333558e-3f);
    p = fmaf(p, f, 9.6181291e-3f);
    p = fmaf(p, f, 5.5504109e-2f);
    p = fmaf(p, f, 2.4022651e-1f);
    p = fmaf(p, f, 6.9314718e-1f);
    p = fmaf(p, f, 1.0f);
    int e = ((int)n + 127) << 23;
    return p * __int_as_float(e);
}

__device__ __forceinline__ __nv_bfloat162 cvt2(const float2 v) {
    __nv_bfloat162 r; r.x = __float2bfloat16(v.x); r.y = __float2bfloat16(v.y);
    return r;
}
__device__ __forceinline__ uint2 cvt4(const float4 v) {
    __nv_bfloat162 lo = cvt2(make_float2(v.x, v.y));
    __nv_bfloat162 hi = cvt2(make_float2(v.z, v.w));
    uint2 r;
    r.x = *(const uint32_t*)&lo;
    r.y = *(const uint32_t*)&hi;
    return r;
}

// ---------------- conversion: H, W1, W2 -> bf16, 4 elems/thread; init folded --
__global__ void cvt_all_kernel(const float* __restrict__ hi_,
                               const float* __restrict__ hj_,
                               const float* __restrict__ W1,
                               const float* __restrict__ W2) {
    size_t i = (size_t)blockIdx.x * 256 + threadIdx.x;   // float4-quad index
    if (i < NTOT) g_S[i] = 0.f;
    if (i < 2 * LAT) { g_sum[i] = 0.f; g_sumsq[i] = 0.f; }
    const size_t nH  = (size_t)NTOT * 512;               // H quads
    const size_t nW1 = (size_t)LAT * 512;                // W1 quads
    if (i < nH) {
        const size_t half = (size_t)BATCH * 512;
        float4 v = (i < half) ? ((const float4*)hi_)[i]
                              : ((const float4*)hj_)[i - half];
        ((uint2*)g_A2)[i] = cvt4(v);
    } else if (i < nH + nW1) {
        size_t j = i - nH;
        ((uint2*)g_B1s)[j] = cvt4(((const float4*)W1)[j]);
    } else {
        size_t j = i - nH - nW1;                         // W2: PROJ*512 quads
        ((uint2*)g_W2s)[j] = cvt4(((const float4*)W2)[j]);
    }
}

// ---------------- 8-warp bf16 MMA mainloop (gemm2 + sim) ----------------------
template <int KPHYS, int KH>
__device__ __forceinline__ void mma_mainloop(const __nv_bfloat16* __restrict__ A,
                                             const __nv_bfloat16* __restrict__ B,
                                             int m0, int n0, int c0, int nck,
                                             float acc[4][4][4]) {
    extern __shared__ char smem[];
    const uint32_t sb = smem_u32(smem);
    const int tid  = threadIdx.x;
    const int lane = tid & 31;
    const int w    = tid >> 5;
    const int wm   = w & 1;
    const int wn   = w >> 1;

    auto load_tile = [&](int c) {
        const int cl = c0 + c;
        const int kA = ((cl < 2 * KH) ? cl : cl - 2 * KH) * 64;
        const int kB = ((cl < KH) ? cl : cl - KH) * 64;
        const uint32_t sA = sb + (uint32_t)(c % 3) * 32768u;
        const uint32_t sB = sA + 16384u;
#pragma unroll
        for (int i = 0; i < 4; i++) {
            int idx = i * 256 + tid;
            int row = idx >> 3, ch = idx & 7;
            uint32_t dst = (uint32_t)row * 128 + (uint32_t)((ch ^ (row & 7)) * 16);
            cp16(sA + dst, A + (size_t)(m0 + row) * KPHYS + kA + ch * 8);
            cp16(sB + dst, B + (size_t)(n0 + row) * KPHYS + kB + ch * 8);
        }
        cp_commit();
    };

#pragma unroll
    for (int i = 0; i < 4; i++)
#pragma unroll
        for (int j = 0; j < 4; j++)
#pragma unroll
            for (int q = 0; q < 4; q++) acc[i][j][q] = 0.f;

    const int rA   = wm * 64 + (lane & 15);
    const int khA  = lane >> 4;
    const int rB   = wn * 32 + ((lane >> 4) << 3) + (lane & 7);
    const int khB  = (lane >> 3) & 1;
    const int rlow = lane & 7;

    load_tile(0);
    load_tile(1);

    for (int c = 0; c < nck; c++) {
        if (c < nck - 1) cp_wait1(); else cp_wait0();
        __syncthreads();
        if (c + 2 < nck) load_tile(c + 2);
        const uint32_t sA = sb + (uint32_t)(c % 3) * 32768u;
        const uint32_t sB = sA + 16384u;
#pragma unroll
        for (int ks = 0; ks < 4; ks++) {
            uint32_t af[4][4], bf[4][2];
#pragma unroll
            for (int mi = 0; mi < 4; mi++) {
                uint32_t a = sA + (uint32_t)(rA + mi * 16) * 128
                           + (uint32_t)((((ks * 2) + khA) ^ rlow) * 16);
                ldsm_x4(a, af[mi][0], af[mi][1], af[mi][2], af[mi][3]);
            }
#pragma unroll
            for (int np = 0; np < 2; np++) {
                uint32_t r0, r1, r2, r3;
                uint32_t a = sB + (uint32_t)(rB + np * 16) * 128
                           + (uint32_t)((((ks * 2) + khB) ^ rlow) * 16);
                ldsm_x4(a, r0, r1, r2, r3);
                bf[np * 2 + 0][0] = r0; bf[np * 2 + 0][1] = r1;
                bf[np * 2 + 1][0] = r2; bf[np * 2 + 1][1] = r3;
            }
#pragma unroll
            for (int mi = 0; mi < 4; mi++)
#pragma unroll
                for (int nf = 0; nf < 4; nf++)
                    mma16816(acc[mi][nf], af[mi], bf[nf]);
        }
    }
}

// ---------------- GEMM1: bf16, 4-warp, ks-pipelined fragments (+BN stats) ----
__global__ __launch_bounds__(128, 2) void gemm1_mma_kernel() {
    extern __shared__ char smem[];
    const uint32_t sb = smem_u32(smem);
    const int tid  = threadIdx.x;
    const int lane = tid & 31;
    const int w    = tid >> 5;
    const int wm   = w & 1;
    const int wn   = w >> 1;
    const int m0 = blockIdx.y * 128, n0 = blockIdx.x * 128;

    auto load_tile = [&](int c) {
        const int k0 = c * 64;
        const uint32_t sA = sb + (uint32_t)(c % 3) * 32768u;
        const uint32_t sB = sA + 16384u;
#pragma unroll
        for (int i = 0; i < 8; i++) {
            int idx = i * 128 + tid;
            int row = idx >> 3, ch = idx & 7;
            uint32_t dst = (uint32_t)row * 128 + (uint32_t)((ch ^ (row & 7)) * 16);
            cp16(sA + dst, g_A2 + (size_t)(m0 + row) * KPG + k0 + ch * 8);
            cp16(sB + dst, g_B1s + (size_t)(n0 + row) * KPG + k0 + ch * 8);
        }
        cp_commit();
    };

    float acc[4][8][4];
#pragma unroll
    for (int i = 0; i < 4; i++)
#pragma unroll
        for (int j = 0; j < 8; j++)
#pragma unroll
            for (int q = 0; q < 4; q++) acc[i][j][q] = 0.f;

    const int rA   = wm * 64 + (lane & 15);
    const int khA  = lane >> 4;
    const int rB   = wn * 64 + ((lane >> 4) << 3) + (lane & 7);
    const int khB  = (lane >> 3) & 1;
    const int rlow = lane & 7;

    auto ldfrags = [&](uint32_t sA, uint32_t sB, int ks,
                       uint32_t af[4][4], uint32_t bf[8][2]) {
#pragma unroll
        for (int mi = 0; mi < 4; mi++) {
            uint32_t a = sA + (uint32_t)(rA + mi * 16) * 128
                       + (uint32_t)((((ks * 2) + khA) ^ rlow) * 16);
            ldsm_x4(a, af[mi][0], af[mi][1], af[mi][2], af[mi][3]);
        }
#pragma unroll
        for (int np = 0; np < 4; np++) {
            uint32_t r0, r1, r2, r3;
            uint32_t a = sB + (uint32_t)(rB + np * 16) * 128
                       + (uint32_t)((((ks * 2) + khB) ^ rlow) * 16);
            ldsm_x4(a, r0, r1, r2, r3);
            bf[np * 2 + 0][0] = r0; bf[np * 2 + 0][1] = r1;
            bf[np * 2 + 1][0] = r2; bf[np * 2 + 1][1] = r3;
        }
    };

    load_tile(0);
    load_tile(1);

    for (int c = 0; c < NCK1; c++) {
        if (c < NCK1 - 1) cp_wait1(); else cp_wait0();
        __syncthreads();
        if (c + 2 < NCK1) load_tile(c + 2);
        const uint32_t sA = sb + (uint32_t)(c % 3) * 32768u;
        const uint32_t sB = sA + 16384u;

        uint32_t af[2][4][4], bf[2][8][2];
        ldfrags(sA, sB, 0, af[0], bf[0]);
#pragma unroll
        for (int ks = 0; ks < 4; ks++) {
            const int cur = ks & 1, nxt = cur ^ 1;
            if (ks < 3) ldfrags(sA, sB, ks + 1, af[nxt], bf[nxt]);
#pragma unroll
            for (int mi = 0; mi < 4; mi++)
#pragma unroll
                for (int nf = 0; nf < 8; nf++)
                    mma16816(acc[mi][nf], af[cur][mi], bf[cur][nf]);
        }
    }

#pragma unroll
    for (int mi = 0; mi < 4; mi++) {
        int row = m0 + wm * 64 + mi * 16 + (lane >> 2);
#pragma unroll
        for (int nf = 0; nf < 8; nf++) {
            int col = n0 + wn * 64 + nf * 8 + (lane & 3) * 2;
            *(__nv_bfloat162*)(g_Xb + (size_t)row * LAT + col) =
                cvt2(make_float2(acc[mi][nf][0], acc[mi][nf][1]));
            *(__nv_bfloat162*)(g_Xb + (size_t)(row + 8) * LAT + col) =
                cvt2(make_float2(acc[mi][nf][2], acc[mi][nf][3]));
        }
    }
    const int g = m0 >> 11;
#pragma unroll
    for (int nf = 0; nf < 8; nf++) {
#pragma unroll
        for (int q = 0; q < 2; q++) {
            float s = 0.f, sq = 0.f;
#pragma unroll
            for (int mi = 0; mi < 4; mi++) {
                float v0 = acc[mi][nf][q];
                float v1 = acc[mi][nf][q + 2];
                s += v0 + v1;
                sq = fmaf(v0, v0, sq);
                sq = fmaf(v1, v1, sq);
            }
#pragma unroll
            for (int off = 4; off <= 16; off <<= 1) {
                s  += __shfl_xor_sync(0xffffffffu, s, off);
                sq += __shfl_xor_sync(0xffffffffu, sq, off);
            }
            if ((lane >> 2) == 0) {
                int col = n0 + wn * 64 + nf * 8 + (lane & 3) * 2 + q;
                atomicAdd(&g_sum[g * LAT + col], s);
                atomicAdd(&g_sumsq[g * LAT + col], sq);
            }
        }
    }
}

// ---------------- GEMM2 (8-warp bf16 core, split-K=4) -------------------------
__global__ __launch_bounds__(256, 2) void gemm2_mma_kernel() {
    float acc[4][4][4];
    const int z  = blockIdx.z;
    const int m0 = blockIdx.y * 128, n0 = blockIdx.x * 128;
    mma_mainloop<KPG, 32>(g_X2, g_W2s, m0, n0, z * 8, 8, acc);
    float* out = g_Zp + (size_t)z * NTOT * PROJ;
    const int lane = threadIdx.x & 31, w = threadIdx.x >> 5;
    const int wm = w & 1, wn = w >> 1;
#pragma unroll
    for (int mi = 0; mi < 4; mi++) {
        int row = m0 + wm * 64 + mi * 16 + (lane >> 2);
#pragma unroll
        for (int nf = 0; nf < 4; nf++) {
            int col = n0 + wn * 32 + nf * 8 + (lane & 3) * 2;
            *(float2*)(out + (size_t)row * PROJ + col) =
                make_float2(acc[mi][nf][0], acc[mi][nf][1]);
            *(float2*)(out + (size_t)(row + 8) * PROJ + col) =
                make_float2(acc[mi][nf][2], acc[mi][nf][3]);
        }
    }
}

// ---------------- BN finalize ---------------------------------------------------
__global__ void bnfinal_kernel(const float* __restrict__ gamma,
                               const float* __restrict__ beta) {
    int idx = blockIdx.x * 256 + threadIdx.x;
    int c = idx & (LAT - 1);
    const float inv = 1.0f / (float)BATCH;
    float mu  = g_sum[idx] * inv;
    float var = g_sumsq[idx] * inv - mu * mu;
    float a = gamma[c] * rsqrtf(var + 1e-5f);
    g_bna[idx] = a;
    g_bnc[idx] = beta[c] - mu * a;
}

// ---------------- fused BN + ReLU: block = 8 rows, coeffs loaded once ---------
// Block b: rows 8b..8b+7 (same BN group). Thread t: columns 8t..8t+7 across
// all 8 rows -> 4 coefficient loads serve 8 row-iterations (uint4 in/out).
__global__ void bnrelu_kernel() {
    const int b   = blockIdx.x;                // 0..511
    const int t   = threadIdx.x;               // 0..255
    const int g   = b >> 8;                    // row group (rows 8b.. all same)
    const int c0  = t * 8;
    const float4* A4 = (const float4*)(g_bna + g * LAT + c0);
    const float4* C4 = (const float4*)(g_bnc + g * LAT + c0);
    const float4 a0 = A4[0], a1 = A4[1];
    const float4 k0 = C4[0], k1 = C4[1];
    const uint4* X4 = (const uint4*)g_Xb;
    uint4* O4 = (uint4*)g_X2;
    size_t idx = (size_t)(b * 8) * 256 + t;    // uint4 index (256 per row)

#pragma unroll
    for (int r = 0; r < 8; r++, idx += 256) {
        uint4 xb = X4[idx];
        uint4 out;
        {
            __nv_bfloat162 x = *(const __nv_bfloat162*)&xb.x;
            __nv_bfloat162 v = cvt2(make_float2(
                fmaxf(fmaf(__bfloat162float(x.x), a0.x, k0.x), 0.f),
                fmaxf(fmaf(__bfloat162float(x.y), a0.y, k0.y), 0.f)));
            out.x = *(const uint32_t*)&v;
        }
        {
            __nv_bfloat162 x = *(const __nv_bfloat162*)&xb.y;
            __nv_bfloat162 v = cvt2(make_float2(
                fmaxf(fmaf(__bfloat162float(x.x), a0.z, k0.z), 0.f),
                fmaxf(fmaf(__bfloat162float(x.y), a0.w, k0.w), 0.f)));
            out.y = *(const uint32_t*)&v;
        }
        {
            __nv_bfloat162 x = *(const __nv_bfloat162*)&xb.z;
            __nv_bfloat162 v = cvt2(make_float2(
                fmaxf(fmaf(__bfloat162float(x.x), a1.x, k1.x), 0.f),
                fmaxf(fmaf(__bfloat162float(x.y), a1.y, k1.y), 0.f)));
            out.z = *(const uint32_t*)&v;
        }
        {
            __nv_bfloat162 x = *(const __nv_bfloat162*)&xb.w;
            __nv_bfloat162 v = cvt2(make_float2(
                fmaxf(fmaf(__bfloat162float(x.x), a1.z, k1.z), 0.f),
                fmaxf(fmaf(__bfloat162float(x.y), a1.w, k1.w), 0.f)));
            out.w = *(const uint32_t*)&v;
        }
        O4[idx] = out;
    }
}

// ---------------- rownorm: sum 4 split-K parts + bias, normalize, emit bf16 ---
__global__ void rownorm_kernel(const float* __restrict__ b2) {
    int row  = blockIdx.x * 8 + (threadIdx.x >> 5);
    int lane = threadIdx.x & 31;
    const float4* bb = (const float4*)b2;
    float4 v0, v1;
    {
        float4 c = bb[lane], f = bb[lane + 32];
        v0 = c; v1 = f;
#pragma unroll
        for (int z = 0; z < SPLK2; z++) {
            const float4* p = (const float4*)(g_Zp + ((size_t)z * NTOT + row) * PROJ);
            float4 a = p[lane], d = p[lane + 32];
            v0.x += a.x; v0.y += a.y; v0.z += a.z; v0.w += a.w;
            v1.x += d.x; v1.y += d.y; v1.z += d.z; v1.w += d.w;
        }
    }
    float ss = v0.x * v0.x + v0.y * v0.y + v0.z * v0.z + v0.w * v0.w
             + v1.x * v1.x + v1.y * v1.y + v1.z * v1.z + v1.w * v1.w;
#pragma unroll
    for (int off = 16; off; off >>= 1) ss += __shfl_xor_sync(0xffffffffu, ss, off);
    float s = 1.41421356237f / fmaxf(sqrtf(ss), 1e-8f);   // sqrt(1/TEMP)/||z||
    v0.x *= s; v0.y *= s; v0.z *= s; v0.w *= s;
    v1.x *= s; v1.y *= s; v1.z *= s; v1.w *= s;

    __nv_bfloat162* Z = (__nv_bfloat162*)(g_Zs + (size_t)row * KPZ);
    Z[lane * 2 + 0]        = cvt2(make_float2(v0.x, v0.y));
    Z[lane * 2 + 1]        = cvt2(make_float2(v0.z, v0.w));
    Z[(lane + 32) * 2 + 0] = cvt2(make_float2(v1.x, v1.y));
    Z[(lane + 32) * 2 + 1] = cvt2(make_float2(v1.z, v1.w));
}

// ---------------- symmetric tensorized sim + online exp-sum ------------------
__global__ __launch_bounds__(256, 2) void sim_mma_kernel() {
    const int a = blockIdx.y, b = blockIdx.x;
    if (b < a) return;
    float acc[4][4][4];
    const int i0 = a * 128, j0 = b * 128;
    mma_mainloop<KPZ, 4>(g_Zs, g_Zs, i0, j0, 0, NCKZ, acc);

    const int lane = threadIdx.x & 31, w = threadIdx.x >> 5;
    const int wm = w & 1, wn = w >> 1;
    const int lr = lane >> 2;
    const int lc = (lane & 3) * 2;
    const bool offd = (a != b);

    float cs[4][2];
#pragma unroll
    for (int nf = 0; nf < 4; nf++) { cs[nf][0] = 0.f; cs[nf][1] = 0.f; }

#pragma unroll
    for (int mi = 0; mi < 4; mi++) {
        int row0 = i0 + wm * 64 + mi * 16 + lr;
        int row1 = row0 + 8;
        int p0 = (row0 < BATCH) ? row0 + BATCH : row0 - BATCH;
        int p1 = (row1 < BATCH) ? row1 + BATCH : row1 - BATCH;
        float rs0 = 0.f, rs1 = 0.f;
#pragma unroll
        for (int nf = 0; nf < 4; nf++) {
            int col = j0 + wn * 32 + nf * 8 + lc;
            float d00 = acc[mi][nf][0], d01 = acc[mi][nf][1];
            float d10 = acc[mi][nf][2], d11 = acc[mi][nf][3];
            if (col == p0)     { g_pos[row0] = d00; g_pos[col]     = d00; }
            if (col + 1 == p0) { g_pos[row0] = d01; g_pos[col + 1] = d01; }
            if (col == p1)     { g_pos[row1] = d10; g_pos[col]     = d10; }
            if (col + 1 == p1) { g_pos[row1] = d11; g_pos[col + 1] = d11; }
            float e00 = (col     != row0) ? fexp(d00 - 2.f) : 0.f;
            float e01 = (col + 1 != row0) ? fexp(d01 - 2.f) : 0.f;
            float e10 = (col     != row1) ? fexp(d10 - 2.f) : 0.f;
            float e11 = (col + 1 != row1) ? fexp(d11 - 2.f) : 0.f;
            rs0 += e00 + e01;
            rs1 += e10 + e11;
            if (offd) { cs[nf][0] += e00 + e10; cs[nf][1] += e01 + e11; }
        }
        rs0 += __shfl_xor_sync(0xffffffffu, rs0, 1);
        rs0 += __shfl_xor_sync(0xffffffffu, rs0, 2);
        rs1 += __shfl_xor_sync(0xffffffffu, rs1, 1);
        rs1 += __shfl_xor_sync(0xffffffffu, rs1, 2);
        if ((lane & 3) == 0) {
            atomicAdd(&g_S[row0], rs0);
            atomicAdd(&g_S[row1], rs1);
        }
    }
    if (offd) {
#pragma unroll
        for (int nf = 0; nf < 4; nf++) {
#pragma unroll
            for (int q = 0; q < 2; q++) {
                float v = cs[nf][q];
                v += __shfl_xor_sync(0xffffffffu, v, 4);
                v += __shfl_xor_sync(0xffffffffu, v, 8);
                v += __shfl_xor_sync(0xffffffffu, v, 16);
                if (lr == 0)
                    atomicAdd(&g_S[j0 + wn * 32 + nf * 8 + lc + q], v);
            }
        }
    }
}

// ---------------- final reduction --------------------------------------------
__global__ void loss_kernel(float* __restrict__ out) {
    __shared__ float red[256];
    int t = threadIdx.x;
    float s = 0.f;
    for (int i = t; i < NTOT; i += 256)
        s += 2.0f + logf(g_S[i]) - g_pos[i];
    red[t] = s;
    __syncthreads();
    for (int off = 128; off; off >>= 1) {
        if (t < off) red[t] += red[t + off];
        __syncthreads();
    }
    if (t == 0) out[0] = red[0] / (float)NTOT;
}

// ---------------- launch ------------------------------------------------------
extern "C" void kernel_launch(void* const* d_in, const int* in_sizes, int n_in,
                              void* d_out, int out_size) {
    const float* h_i   = (const float*)d_in[0];
    const float* h_j   = (const float*)d_in[1];
    const float* W1    = (const float*)d_in[2];
    const float* gamma = (const float*)d_in[3];
    const float* beta  = (const float*)d_in[4];
    const float* W2    = (const float*)d_in[5];
    const float* b2    = (const float*)d_in[6];
    float* out = (float*)d_out;

    const int GEMM_SMEM = 3 * 32768;   // 98304
    cudaFuncSetAttribute(gemm1_mma_kernel, cudaFuncAttributeMaxDynamicSharedMemorySize, GEMM_SMEM);
    cudaFuncSetAttribute(gemm2_mma_kernel, cudaFuncAttributeMaxDynamicSharedMemorySize, GEMM_SMEM);
    cudaFuncSetAttribute(sim_mma_kernel,   cudaFuncAttributeMaxDynamicSharedMemorySize, GEMM_SMEM);

    const int CVT_QUADS = (NTOT + LAT + PROJ) * 512;     // H + W1 + W2 float4s
    cvt_all_kernel<<<CVT_QUADS / 256, 256>>>(h_i, h_j, W1, W2);
    gemm1_mma_kernel<<<dim3(16, 32), 128, GEMM_SMEM>>>();
    bnfinal_kernel<<<16, 256>>>(gamma, beta);
    bnrelu_kernel<<<NTOT / 8, 256>>>();
    gemm2_mma_kernel<<<dim3(2, 32, SPLK2), 256, GEMM_SMEM>>>();
    rownorm_kernel<<<512, 256>>>(b2);
    sim_mma_kernel<<<dim3(32, 32), 256, GEMM_SMEM>>>();
    loss_kernel<<<1, 256>>>(out);
}